// round 1
// baseline (speedup 1.0000x reference)
#include <cuda_runtime.h>
#include <cuda_bf16.h>
#include <cstdint>

#define Tn    512
#define Bn    64
#define EMBD  256
#define HD    256
#define G4    1024   // 4*HD
#define NTAG  32
#define STOPID 30

// -------- scratch (device globals; no allocation) --------
__device__ float g_xw[(size_t)2 * Tn * Bn * G4];     // [dir][t][b][1024]  268MB
__device__ float g_h[(size_t)Tn * Bn * (2 * HD)];    // [t][b][512]        64MB
__device__ float g_htag[(size_t)Tn * Bn * NTAG];     // [t][b][32]         4MB

__device__ __forceinline__ float sigf(float x) { return 1.f / (1.f + __expf(-x)); }
__device__ __forceinline__ float tanhf_(float x) { return 2.f * sigf(2.f * x) - 1.f; }

// ============================================================
// Kernel 1: xW = emb[inp] @ Wih^T + b   for both directions
// C[32768 rows=(t,b)][2048 cols] ; 128x128 tile, 8x8 micro
// ============================================================
__global__ void __launch_bounds__(256) k_input_gemm(
    const int* __restrict__ inp, const float* __restrict__ emb,
    const float* __restrict__ Wf, const float* __restrict__ bf,
    const float* __restrict__ Wb, const float* __restrict__ bb)
{
    __shared__ float As[8][128];
    __shared__ float Bs[8][132];
    __shared__ int   tok[128];

    int tid = threadIdx.x;
    int rowBase = blockIdx.x * 128;
    int cg0 = blockIdx.y * 128;
    int dir = cg0 >> 10;
    const float* W    = dir ? Wb : Wf;
    const float* bias = dir ? bb : bf;
    int colW0 = cg0 & (G4 - 1);

    if (tid < 128) {
        int r = rowBase + tid;
        int t = r >> 6, b = r & 63;
        tok[tid] = inp[b * Tn + t];
    }
    __syncthreads();

    float acc[8][8];
#pragma unroll
    for (int i = 0; i < 8; i++)
#pragma unroll
        for (int j = 0; j < 8; j++) acc[i][j] = 0.f;

    int lr = tid >> 1, kq = tid & 1;
    int ty = tid >> 4, tx = tid & 15;
    const float* embRow = emb + (size_t)tok[lr] * EMBD + kq * 4;
    const float* wRow   = W + (size_t)(colW0 + lr) * EMBD + kq * 4;

    for (int kc = 0; kc < EMBD; kc += 8) {
        float4 av = *(const float4*)(embRow + kc);
        float4 bv = *(const float4*)(wRow + kc);
        As[kq * 4 + 0][lr] = av.x; As[kq * 4 + 1][lr] = av.y;
        As[kq * 4 + 2][lr] = av.z; As[kq * 4 + 3][lr] = av.w;
        Bs[kq * 4 + 0][lr] = bv.x; Bs[kq * 4 + 1][lr] = bv.y;
        Bs[kq * 4 + 2][lr] = bv.z; Bs[kq * 4 + 3][lr] = bv.w;
        __syncthreads();
#pragma unroll
        for (int k = 0; k < 8; k++) {
            float a[8], bb2[8];
            *(float4*)(a)     = *(const float4*)&As[k][ty * 8];
            *(float4*)(a + 4) = *(const float4*)&As[k][ty * 8 + 4];
            *(float4*)(bb2)     = *(const float4*)&Bs[k][tx * 8];
            *(float4*)(bb2 + 4) = *(const float4*)&Bs[k][tx * 8 + 4];
#pragma unroll
            for (int i = 0; i < 8; i++)
#pragma unroll
                for (int j = 0; j < 8; j++)
                    acc[i][j] = fmaf(a[i], bb2[j], acc[i][j]);
        }
        __syncthreads();
    }

    float bvals[8];
#pragma unroll
    for (int j = 0; j < 8; j++) bvals[j] = bias[colW0 + tx * 8 + j];

#pragma unroll
    for (int i = 0; i < 8; i++) {
        int r = rowBase + ty * 8 + i;
        int t = r >> 6, b = r & 63;
        float* op = g_xw + (((size_t)dir * Tn + t) * Bn + b) * G4 + colW0 + tx * 8;
        float4 o0, o1;
        o0.x = acc[i][0] + bvals[0]; o0.y = acc[i][1] + bvals[1];
        o0.z = acc[i][2] + bvals[2]; o0.w = acc[i][3] + bvals[3];
        o1.x = acc[i][4] + bvals[4]; o1.y = acc[i][5] + bvals[5];
        o1.z = acc[i][6] + bvals[6]; o1.w = acc[i][7] + bvals[7];
        *(float4*)op       = o0;
        *(float4*)(op + 4) = o1;
    }
}

// ============================================================
// Kernel 2: BiLSTM recurrence.
// Cluster of 8 CTAs handles (dir, batch-group of 8).
// CTA s owns h elems [32s, 32s+32): 128 gate rows of Whh in SMEM.
// h exchanged per-step via DSMEM, double-buffered, 1 cluster sync/step.
// ============================================================
#define LSTM_WS_FLOATS   (128 * 260)
#define LSTM_HALL_FLOATS (2 * 8 * 260)
#define LSTM_GS_FLOATS   (8 * 4 * 32)
#define LSTM_SMEM ((LSTM_WS_FLOATS + LSTM_HALL_FLOATS + LSTM_GS_FLOATS) * 4)

__global__ void __cluster_dims__(8, 1, 1) __launch_bounds__(128, 1)
k_lstm(const int* __restrict__ mask,
       const float* __restrict__ WhhF, const float* __restrict__ WhhB)
{
    extern __shared__ float sm[];
    float* Ws   = sm;                                   // [128][260]
    float* hall = sm + LSTM_WS_FLOATS;                  // [2][8][260]
    float* gs   = hall + LSTM_HALL_FLOATS;              // [8][4][32]

    int tid = threadIdx.x;
    int s   = blockIdx.x;           // cluster rank == slice
    int dir = blockIdx.y >> 3;
    int bg  = blockIdx.y & 7;
    int bglob0 = bg * 8;

    const float* Whh = dir ? WhhB : WhhF;
    int gate = tid >> 5, hj = tid & 31;
    int grow = gate * HD + s * 32 + hj;

    // load this CTA's 128-row weight slice
    {
        const float* src = Whh + (size_t)grow * HD;
        float* dst = Ws + tid * 260;
#pragma unroll 4
        for (int k = 0; k < HD; k += 4)
            *(float4*)(dst + k) = *(const float4*)(src + k);
    }
    for (int i = tid; i < LSTM_HALL_FLOATS; i += 128) hall[i] = 0.f;

    float c0 = 0.f, c1 = 0.f, hp0 = 0.f, hp1 = 0.f;

    uint32_t smem_u32;
    asm("{ .reg .u64 t; cvta.to.shared.u64 t, %1; cvt.u32.u64 %0, t; }"
        : "=r"(smem_u32) : "l"(sm));
    int bb  = tid >> 4;
    int hj0 = (tid & 15) * 2;
    uint32_t dst_base = smem_u32 +
        (uint32_t)((LSTM_WS_FLOATS + bb * 260 + s * 32 + hj0) * 4);

    __syncthreads();
    asm volatile("barrier.cluster.arrive.aligned;" ::: "memory");
    asm volatile("barrier.cluster.wait.aligned;" ::: "memory");

    int p = 0;
    for (int step = 0; step < Tn; step++) {
        int t = dir ? (Tn - 1 - step) : step;

        // prefetch input projection for this step (consumed after matmul)
        const float* xwp = g_xw + (((size_t)dir * Tn + t) * Bn + bglob0) * G4 + grow;
        float xv[8];
#pragma unroll
        for (int b = 0; b < 8; b++) xv[b] = xwp[b * G4];

        const float* hsrc = hall + p * (8 * 260);
        const float* wrow = Ws + tid * 260;
        float acc[8] = {0.f, 0.f, 0.f, 0.f, 0.f, 0.f, 0.f, 0.f};
#pragma unroll 4
        for (int k = 0; k < HD; k += 4) {
            float4 w = *(const float4*)(wrow + k);
#pragma unroll
            for (int b = 0; b < 8; b++) {
                float4 h4 = *(const float4*)(hsrc + b * 260 + k);
                acc[b] = fmaf(h4.x, w.x, acc[b]);
                acc[b] = fmaf(h4.y, w.y, acc[b]);
                acc[b] = fmaf(h4.z, w.z, acc[b]);
                acc[b] = fmaf(h4.w, w.w, acc[b]);
            }
        }
#pragma unroll
        for (int b = 0; b < 8; b++) gs[(b * 4 + gate) * 32 + hj] = acc[b] + xv[b];
        __syncthreads();

        // phase B: thread -> (bb, hj0..hj0+1)
        float gi0 = gs[(bb * 4 + 0) * 32 + hj0], gi1 = gs[(bb * 4 + 0) * 32 + hj0 + 1];
        float gf0 = gs[(bb * 4 + 1) * 32 + hj0], gf1 = gs[(bb * 4 + 1) * 32 + hj0 + 1];
        float gg0 = gs[(bb * 4 + 2) * 32 + hj0], gg1 = gs[(bb * 4 + 2) * 32 + hj0 + 1];
        float go0 = gs[(bb * 4 + 3) * 32 + hj0], go1 = gs[(bb * 4 + 3) * 32 + hj0 + 1];
        float m = (float)mask[(bglob0 + bb) * Tn + t];

        float cn0 = sigf(gf0) * c0 + sigf(gi0) * tanhf_(gg0);
        float hn0 = sigf(go0) * tanhf_(cn0);
        c0 = m * cn0 + (1.f - m) * c0;
        float h0 = m * hn0 + (1.f - m) * hp0; hp0 = h0;

        float cn1 = sigf(gf1) * c1 + sigf(gi1) * tanhf_(gg1);
        float hn1 = sigf(go1) * tanhf_(cn1);
        c1 = m * cn1 + (1.f - m) * c1;
        float h1 = m * hn1 + (1.f - m) * hp1; hp1 = h1;

        // store h to global (both dirs concatenated)
        float2 hv; hv.x = h0; hv.y = h1;
        *(float2*)&g_h[((size_t)t * Bn + bglob0 + bb) * (2 * HD) + dir * HD + s * 32 + hj0] = hv;

        // DSMEM broadcast into every cluster CTA's hall[p^1]
        unsigned long long pk;
        asm("mov.b64 %0, {%1,%2};" : "=l"(pk) : "f"(h0), "f"(h1));
        uint32_t daddr = dst_base + (uint32_t)((p ^ 1) * (8 * 260) * 4);
#pragma unroll
        for (int peer = 0; peer < 8; peer++) {
            uint32_t ra;
            asm volatile("mapa.shared::cluster.u32 %0, %1, %2;"
                         : "=r"(ra) : "r"(daddr), "r"(peer));
            asm volatile("st.shared::cluster.b64 [%0], %1;"
                         :: "r"(ra), "l"(pk) : "memory");
        }
        asm volatile("barrier.cluster.arrive.aligned;" ::: "memory");
        asm volatile("barrier.cluster.wait.aligned;" ::: "memory");
        p ^= 1;
    }
}

// ============================================================
// Kernel 3: h_tag = (h @ W_tag^T + b_tag) * mask
// 8 rows x 32 cols per CTA, K=512
// ============================================================
#define TAG_SMEM ((32 * 520 + 8 * 516) * 4)
__global__ void __launch_bounds__(256) k_tag(
    const int* __restrict__ mask, const float* __restrict__ Wt,
    const float* __restrict__ bt)
{
    extern __shared__ float smt[];
    float* Ws = smt;             // [32][520]
    float* Hs = smt + 32 * 520;  // [8][516]
    int tid = threadIdx.x;
    int row0 = blockIdx.x * 8;

    for (int idx = tid; idx < 32 * 128; idx += 256) {
        int r = idx >> 7, f = idx & 127;
        *(float4*)&Ws[r * 520 + f * 4] = *(const float4*)&Wt[r * 512 + f * 4];
    }
    for (int idx = tid; idx < 8 * 128; idx += 256) {
        int r = idx >> 7, f = idx & 127;
        *(float4*)&Hs[r * 516 + f * 4] = *(const float4*)&g_h[(size_t)(row0 + r) * 512 + f * 4];
    }
    __syncthreads();

    int r8 = tid >> 5, col = tid & 31;
    float acc = 0.f;
    const float* wr = Ws + col * 520;
    const float* hr = Hs + r8 * 516;
#pragma unroll 8
    for (int k = 0; k < 512; k += 4) {
        float4 w = *(const float4*)(wr + k);
        float4 h = *(const float4*)(hr + k);
        acc = fmaf(w.x, h.x, acc);
        acc = fmaf(w.y, h.y, acc);
        acc = fmaf(w.z, h.z, acc);
        acc = fmaf(w.w, h.w, acc);
    }
    int row = row0 + r8;
    int t = row >> 6, b = row & 63;
    float m = (float)mask[b * Tn + t];
    g_htag[(size_t)row * 32 + col] = (acc + bt[col]) * m;
}

// ============================================================
// Kernel 4: CRF forward (Z) + gold score ; one CTA per batch elem
// ============================================================
__global__ void __launch_bounds__(128) k_crf(
    const int* __restrict__ mask, const int* __restrict__ gold,
    const float* __restrict__ trans, float* __restrict__ out)
{
    __shared__ float tr_s[32 * 33];
    __shared__ float score[32];
    __shared__ float pm[4 * 32];
    __shared__ float ps[4 * 32];
    __shared__ float red[128];
    __shared__ int   redi[128];
    __shared__ float Zsh;

    int tid = threadIdx.x;
    int b = blockIdx.x;
    int j = tid & 31, q = tid >> 5;

    for (int idx = tid; idx < 1024; idx += 128)
        tr_s[(idx >> 5) * 33 + (idx & 31)] = trans[idx];
    if (tid < 32) score[tid] = (tid == STOPID) ? 0.f : -10000.f;
    __syncthreads();

    for (int t = 0; t < Tn; t++) {
        float e = g_htag[((size_t)t * Bn + b) * 32 + j];
        const float* trj = tr_s + j * 33 + q * 8;
        const float* sc  = score + q * 8;
        float v[8];
        float mm = -3.4e38f;
#pragma unroll
        for (int i = 0; i < 8; i++) { v[i] = sc[i] + trj[i]; mm = fmaxf(mm, v[i]); }
        pm[q * 32 + j] = mm;
        __syncthreads();
        float M = fmaxf(fmaxf(pm[j], pm[32 + j]), fmaxf(pm[64 + j], pm[96 + j]));
        float ssum = 0.f;
#pragma unroll
        for (int i = 0; i < 8; i++) ssum += __expf(v[i] - M);
        ps[q * 32 + j] = ssum;
        __syncthreads();
        if (q == 0) {
            float S = ps[j] + ps[32 + j] + ps[64 + j] + ps[96 + j];
            float snew = e + M + __logf(S);
            float mf = (float)mask[b * Tn + t];
            score[j] = mf * snew + (1.f - mf) * score[j];
        }
        __syncthreads();
    }

    // Z = logsumexp(score + trans[STOP])
    if (tid < 32) {
        float v = score[j] + tr_s[STOPID * 33 + j];
        float M = v;
#pragma unroll
        for (int o = 16; o > 0; o >>= 1) M = fmaxf(M, __shfl_xor_sync(0xffffffffu, M, o));
        float e = __expf(v - M);
#pragma unroll
        for (int o = 16; o > 0; o >>= 1) e += __shfl_xor_sync(0xffffffffu, e, o);
        if (tid == 0) Zsh = M + __logf(e);
    }

    // gold path score
    float gacc = 0.f; int lcnt = 0;
    for (int t = tid; t < Tn; t += 128) {
        int m = mask[b * Tn + t];
        lcnt += m;
        if (t < Tn - 1 && m) {
            int gn = gold[b * Tn + t + 1];
            int gc = gold[b * Tn + t];
            gacc += g_htag[((size_t)t * Bn + b) * 32 + gn] + tr_s[gn * 33 + gc];
        }
    }
    red[tid] = gacc; redi[tid] = lcnt;
    __syncthreads();
    if (tid == 0) {
        float gsum = 0.f; int len = 0;
        for (int i = 0; i < 128; i++) { gsum += red[i]; len += redi[i]; }
        int last = gold[b * Tn + len - 1];
        gsum += tr_s[STOPID * 33 + last];
        out[b] = Zsh - gsum;
    }
}

// ============================================================
extern "C" void kernel_launch(void* const* d_in, const int* in_sizes, int n_in,
                              void* d_out, int out_size)
{
    const int*   inp   = (const int*)d_in[0];
    const int*   gold  = (const int*)d_in[1];
    const int*   mask  = (const int*)d_in[2];
    const float* emb   = (const float*)d_in[3];
    const float* Wih_f = (const float*)d_in[4];
    const float* Whh_f = (const float*)d_in[5];
    const float* b_f   = (const float*)d_in[6];
    const float* Wih_b = (const float*)d_in[7];
    const float* Whh_b = (const float*)d_in[8];
    const float* b_b   = (const float*)d_in[9];
    const float* W_tag = (const float*)d_in[10];
    const float* b_tag = (const float*)d_in[11];
    const float* trans = (const float*)d_in[12];
    float* out = (float*)d_out;

    cudaFuncSetAttribute(k_lstm, cudaFuncAttributeMaxDynamicSharedMemorySize, LSTM_SMEM);
    cudaFuncSetAttribute(k_tag,  cudaFuncAttributeMaxDynamicSharedMemorySize, TAG_SMEM);

    k_input_gemm<<<dim3(256, 16, 1), 256>>>(inp, emb, Wih_f, b_f, Wih_b, b_b);
    k_lstm<<<dim3(8, 16, 1), 128, LSTM_SMEM>>>(mask, Whh_f, Whh_b);
    k_tag<<<4096, 256, TAG_SMEM>>>(mask, W_tag, b_tag);
    k_crf<<<64, 128>>>(mask, gold, trans, out);
}

// round 6
// speedup vs baseline: 1.1084x; 1.1084x over previous
#include <cuda_runtime.h>
#include <cuda_bf16.h>
#include <cstdint>

#define Tn    512
#define Bn    64
#define EMBD  256
#define HD    256
#define G4    1024   // 4*HD
#define NTAG  32
#define STOPID 30

typedef unsigned long long ull;

// -------- scratch (device globals; no allocation) --------
__device__ float g_xw[(size_t)2 * Tn * Bn * G4];     // [dir][t][b][1024]  268MB
__device__ float g_h[(size_t)Tn * Bn * (2 * HD)];    // [t][b][512]        64MB
__device__ float g_htag[(size_t)Tn * Bn * NTAG];     // [t][b][32]         4MB

__device__ __forceinline__ float sigf(float x) { return 1.f / (1.f + __expf(-x)); }
__device__ __forceinline__ float tanhf_(float x) { return 2.f * sigf(2.f * x) - 1.f; }

__device__ __forceinline__ ull ffma2(ull a, ull b, ull c) {
    ull d; asm("fma.rn.f32x2 %0,%1,%2,%3;" : "=l"(d) : "l"(a), "l"(b), "l"(c)); return d;
}
__device__ __forceinline__ ull pk2(float lo, float hi) {
    ull r; asm("mov.b64 %0,{%1,%2};" : "=l"(r) : "f"(lo), "f"(hi)); return r;
}
__device__ __forceinline__ float2 unpk(ull v) {
    float2 f; asm("mov.b64 {%0,%1},%2;" : "=f"(f.x), "=f"(f.y) : "l"(v)); return f;
}
// C-level 16B shared load: proper memory semantics, compiles to LDS.128.
__device__ __forceinline__ void lds_pair(const float* p, ull& x, ull& y) {
    ulonglong2 v = *reinterpret_cast<const ulonglong2*>(p);
    x = v.x; y = v.y;
}
__device__ __forceinline__ uint32_t smem_u32_of(const void* p) {
    uint32_t a;
    asm("{ .reg .u64 t; cvta.to.shared.u64 t, %1; cvt.u32.u64 %0, t; }" : "=r"(a) : "l"(p));
    return a;
}

// ============================================================
// Kernel 1: xW = emb[inp] @ Wih^T + b   for both directions
// C[32768 rows=(t,b)][2048 cols] ; 128x128 tile, 8x8 micro, FFMA2
// ============================================================
__global__ void __launch_bounds__(256) k_input_gemm(
    const int* __restrict__ inp, const float* __restrict__ emb,
    const float* __restrict__ Wf, const float* __restrict__ bf,
    const float* __restrict__ Wb, const float* __restrict__ bb)
{
    __shared__ float As[8][128];
    __shared__ float Bs[8][132];
    __shared__ int   tok[128];

    int tid = threadIdx.x;
    int rowBase = blockIdx.x * 128;
    int cg0 = blockIdx.y * 128;
    int dir = cg0 >> 10;
    const float* W    = dir ? Wb : Wf;
    const float* bias = dir ? bb : bf;
    int colW0 = cg0 & (G4 - 1);

    if (tid < 128) {
        int r = rowBase + tid;
        int t = r >> 6, b = r & 63;
        tok[tid] = inp[b * Tn + t];
    }
    __syncthreads();

    ull acc2[8][4];
#pragma unroll
    for (int i = 0; i < 8; i++)
#pragma unroll
        for (int j = 0; j < 4; j++) acc2[i][j] = 0ull;

    int lr = tid >> 1, kq = tid & 1;
    int ty = tid >> 4, tx = tid & 15;
    const float* embRow = emb + (size_t)tok[lr] * EMBD + kq * 4;
    const float* wRow   = W + (size_t)(colW0 + lr) * EMBD + kq * 4;

    for (int kc = 0; kc < EMBD; kc += 8) {
        float4 av = *(const float4*)(embRow + kc);
        float4 bv = *(const float4*)(wRow + kc);
        As[kq * 4 + 0][lr] = av.x; As[kq * 4 + 1][lr] = av.y;
        As[kq * 4 + 2][lr] = av.z; As[kq * 4 + 3][lr] = av.w;
        Bs[kq * 4 + 0][lr] = bv.x; Bs[kq * 4 + 1][lr] = bv.y;
        Bs[kq * 4 + 2][lr] = bv.z; Bs[kq * 4 + 3][lr] = bv.w;
        __syncthreads();
#pragma unroll
        for (int k = 0; k < 8; k++) {
            float a[8];
            *(float4*)(a)     = *(const float4*)&As[k][ty * 8];
            *(float4*)(a + 4) = *(const float4*)&As[k][ty * 8 + 4];
            float4 bv0 = *(const float4*)&Bs[k][tx * 8];
            float4 bv1 = *(const float4*)&Bs[k][tx * 8 + 4];
            ull bp[4];
            bp[0] = pk2(bv0.x, bv0.y); bp[1] = pk2(bv0.z, bv0.w);
            bp[2] = pk2(bv1.x, bv1.y); bp[3] = pk2(bv1.z, bv1.w);
#pragma unroll
            for (int i = 0; i < 8; i++) {
                ull ai = pk2(a[i], a[i]);
#pragma unroll
                for (int j = 0; j < 4; j++)
                    acc2[i][j] = ffma2(ai, bp[j], acc2[i][j]);
            }
        }
        __syncthreads();
    }

    float bvals[8];
#pragma unroll
    for (int j = 0; j < 8; j++) bvals[j] = bias[colW0 + tx * 8 + j];

#pragma unroll
    for (int i = 0; i < 8; i++) {
        int r = rowBase + ty * 8 + i;
        int t = r >> 6, b = r & 63;
        float* op = g_xw + (((size_t)dir * Tn + t) * Bn + b) * G4 + colW0 + tx * 8;
        float2 p0 = unpk(acc2[i][0]), p1 = unpk(acc2[i][1]);
        float2 p2 = unpk(acc2[i][2]), p3 = unpk(acc2[i][3]);
        float4 o0, o1;
        o0.x = p0.x + bvals[0]; o0.y = p0.y + bvals[1];
        o0.z = p1.x + bvals[2]; o0.w = p1.y + bvals[3];
        o1.x = p2.x + bvals[4]; o1.y = p2.y + bvals[5];
        o1.z = p3.x + bvals[6]; o1.w = p3.y + bvals[7];
        *(float4*)op       = o0;
        *(float4*)(op + 4) = o1;
    }
}

// ============================================================
// Kernel 2: BiLSTM recurrence.
// Cluster of 8 CTAs per (dir, batch-group of 8). 256 threads, split-K.
// CTA s owns h slice [32s,32s+32): 128 gate rows of Whh in SMEM.
// h exchanged per-step via DSMEM, double-buffered, 1 cluster sync/step.
// ============================================================
#define LSTM_WS_FLOATS   (128 * 260)
#define LSTM_HALL_FLOATS (2 * 8 * 260)
#define LSTM_PART_FLOATS (8 * 128)
#define LSTM_GS_FLOATS   (8 * 4 * 32)
#define LSTM_SMEM ((LSTM_WS_FLOATS + LSTM_HALL_FLOATS + LSTM_PART_FLOATS + LSTM_GS_FLOATS) * 4)

__global__ void __cluster_dims__(8, 1, 1) __launch_bounds__(256, 1)
k_lstm(const int* __restrict__ mask,
       const float* __restrict__ WhhF, const float* __restrict__ WhhB)
{
    extern __shared__ float sm[];
    float* Ws   = sm;                                   // [128][260]
    float* hall = sm + LSTM_WS_FLOATS;                  // [2][8][260]
    float* part = hall + LSTM_HALL_FLOATS;              // [8][128]
    float* gs   = part + LSTM_PART_FLOATS;              // [8][4][32]

    int tid = threadIdx.x;
    int r   = tid & 127;        // gate-row within slice
    int kh  = tid >> 7;         // K-half
    int s   = blockIdx.x;       // cluster rank == h slice
    int dir = blockIdx.y >> 3;
    int bg  = blockIdx.y & 7;
    int b0  = bg * 8;

    const float* Whh = dir ? WhhB : WhhF;
    int gate = r >> 5, hj = r & 31;
    int grow = gate * HD + s * 32 + hj;

    // load this CTA's weight slice (each thread: half of its row)
    {
        const float* src = Whh + (size_t)grow * HD + kh * 128;
        float* dst = Ws + r * 260 + kh * 128;
#pragma unroll 8
        for (int k = 0; k < 128; k += 4)
            *(float4*)(dst + k) = *(const float4*)(src + k);
    }
    for (int i = tid; i < LSTM_HALL_FLOATS; i += 256) hall[i] = 0.f;

    // epilogue mapping: thread -> (bb, ehj)
    int bb  = tid >> 5;
    int ehj = tid & 31;
    float c = 0.f, hp = 0.f;

    const float* wrow = Ws + r * 260 + kh * 128;

    // peer DSMEM addresses for my (bb, ehj) h value, buffer 0
    uint32_t smem_u32 = smem_u32_of(sm);
    uint32_t hall_b  = smem_u32 + (uint32_t)(LSTM_WS_FLOATS * 4);
    uint32_t my_off = hall_b + (uint32_t)((bb * 260 + s * 32 + ehj) * 4);
    uint32_t peer[8];
#pragma unroll
    for (int pe = 0; pe < 8; pe++)
        asm("mapa.shared::cluster.u32 %0, %1, %2;" : "=r"(peer[pe]) : "r"(my_off), "r"(pe));

    __syncthreads();
    asm volatile("barrier.cluster.arrive.aligned;" ::: "memory");
    asm volatile("barrier.cluster.wait.aligned;" ::: "memory");

    int p = 0;
    for (int step = 0; step < Tn; step++) {
        int t = dir ? (Tn - 1 - step) : step;

        // prefetch mask + input projection (consumed after matmul)
        float m = (float)mask[(b0 + bb) * Tn + t];
        float xv[8];
        if (kh == 0) {
            const float* xwp = g_xw + (((size_t)dir * Tn + t) * Bn + b0) * G4 + grow;
#pragma unroll
            for (int b = 0; b < 8; b++) xv[b] = xwp[b * G4];
        }

        // matmul: partial over this thread's K-half, FFMA2
        const float* hsrc = hall + p * (8 * 260) + kh * 128;
        ull acc[8];
#pragma unroll
        for (int b = 0; b < 8; b++) acc[b] = 0ull;
#pragma unroll 4
        for (int k = 0; k < 128; k += 4) {
            ull w0, w1;
            lds_pair(wrow + k, w0, w1);
#pragma unroll
            for (int b = 0; b < 8; b++) {
                ull h0, h1;
                lds_pair(hsrc + b * 260 + k, h0, h1);
                acc[b] = ffma2(h0, w0, acc[b]);
                acc[b] = ffma2(h1, w1, acc[b]);
            }
        }

        if (kh == 1) {
#pragma unroll
            for (int b = 0; b < 8; b++) {
                float2 f = unpk(acc[b]);
                part[b * 128 + r] = f.x + f.y;
            }
        }
        __syncthreads();
        if (kh == 0) {
#pragma unroll
            for (int b = 0; b < 8; b++) {
                float2 f = unpk(acc[b]);
                gs[(b * 4 + gate) * 32 + hj] = f.x + f.y + part[b * 128 + r] + xv[b];
            }
        }
        __syncthreads();

        // phase B: all 256 threads, one (bb, ehj) each
        float gi = gs[(bb * 4 + 0) * 32 + ehj];
        float gf = gs[(bb * 4 + 1) * 32 + ehj];
        float gg = gs[(bb * 4 + 2) * 32 + ehj];
        float go = gs[(bb * 4 + 3) * 32 + ehj];

        float cn = sigf(gf) * c + sigf(gi) * tanhf_(gg);
        float hn = sigf(go) * tanhf_(cn);
        c = m * cn + (1.f - m) * c;
        float h = m * hn + (1.f - m) * hp; hp = h;

        g_h[((size_t)t * Bn + b0 + bb) * (2 * HD) + dir * HD + s * 32 + ehj] = h;

        uint32_t boff = (uint32_t)((p ^ 1) * (8 * 260) * 4);
#pragma unroll
        for (int pe = 0; pe < 8; pe++) {
            asm volatile("st.shared::cluster.f32 [%0], %1;"
                         :: "r"(peer[pe] + boff), "f"(h) : "memory");
        }
        asm volatile("barrier.cluster.arrive.aligned;" ::: "memory");
        asm volatile("barrier.cluster.wait.aligned;" ::: "memory");
        p ^= 1;
    }
}

// ============================================================
// Kernel 3: h_tag = (h @ W_tag^T + b_tag) * mask  (FFMA2)
// ============================================================
#define TAG_SMEM ((32 * 520 + 8 * 516) * 4)
__global__ void __launch_bounds__(256) k_tag(
    const int* __restrict__ mask, const float* __restrict__ Wt,
    const float* __restrict__ bt)
{
    extern __shared__ float smt[];
    float* Ws = smt;             // [32][520]
    float* Hs = smt + 32 * 520;  // [8][516]
    int tid = threadIdx.x;
    int row0 = blockIdx.x * 8;

    for (int idx = tid; idx < 32 * 128; idx += 256) {
        int r = idx >> 7, f = idx & 127;
        *(float4*)&Ws[r * 520 + f * 4] = *(const float4*)&Wt[r * 512 + f * 4];
    }
    for (int idx = tid; idx < 8 * 128; idx += 256) {
        int r = idx >> 7, f = idx & 127;
        *(float4*)&Hs[r * 516 + f * 4] = *(const float4*)&g_h[(size_t)(row0 + r) * 512 + f * 4];
    }
    __syncthreads();

    int r8 = tid >> 5, col = tid & 31;
    const float* wr = Ws + col * 520;
    const float* hr = Hs + r8 * 516;
    ull acc2 = 0ull, acc2b = 0ull;
#pragma unroll 8
    for (int k = 0; k < 512; k += 4) {
        ull w0, w1, h0, h1;
        lds_pair(wr + k, w0, w1);
        lds_pair(hr + k, h0, h1);
        acc2  = ffma2(w0, h0, acc2);
        acc2b = ffma2(w1, h1, acc2b);
    }
    float2 fa = unpk(acc2), fb = unpk(acc2b);
    float acc = (fa.x + fa.y) + (fb.x + fb.y);
    int row = row0 + r8;
    int t = row >> 6, b = row & 63;
    float m = (float)mask[b * Tn + t];
    g_htag[(size_t)row * 32 + col] = (acc + bt[col]) * m;
}

// ============================================================
// Kernel 4: CRF forward (Z) + gold score
// One warp per batch element; EXACT per-j logsumexp (same math as
// jax.nn.logsumexp over i with per-(b,j) max). Thread j holds trans[j][:]
// in registers; score vector broadcast through smem each step.
// ============================================================
__global__ void __launch_bounds__(32) k_crf(
    const int* __restrict__ mask, const int* __restrict__ gold,
    const float* __restrict__ trans, float* __restrict__ out)
{
    __shared__ float tr_s[32 * 33];
    __shared__ float ssh[32];

    int j = threadIdx.x;        // tag index = lane
    int b = blockIdx.x;

    for (int i = j; i < 1024; i += 32)
        tr_s[(i >> 5) * 33 + (i & 31)] = trans[i];
    __syncwarp();

    float Tj[32];
#pragma unroll
    for (int i = 0; i < 32; i++) Tj[i] = tr_s[j * 33 + i];

    float score = (j == STOPID) ? 0.f : -10000.f;

    float e  = g_htag[(size_t)b * 32 + j];          // t=0 emit
    int   mk = mask[b * Tn];

    for (int t = 0; t < Tn; t++) {
        // prefetch next step's emit/mask (hide global latency under compute)
        float e_nx = 0.f; int mk_nx = 0;
        if (t < Tn - 1) {
            e_nx  = g_htag[((size_t)(t + 1) * Bn + b) * 32 + j];
            mk_nx = mask[b * Tn + t + 1];
        }

        ssh[j] = score;
        __syncwarp();

        // per-j max over v_i = score_i + trans[j][i]  (4-way tree)
        float m0 = -3.4e38f, m1 = -3.4e38f, m2 = -3.4e38f, m3 = -3.4e38f;
#pragma unroll
        for (int i = 0; i < 32; i += 4) {
            m0 = fmaxf(m0, ssh[i]     + Tj[i]);
            m1 = fmaxf(m1, ssh[i + 1] + Tj[i + 1]);
            m2 = fmaxf(m2, ssh[i + 2] + Tj[i + 2]);
            m3 = fmaxf(m3, ssh[i + 3] + Tj[i + 3]);
        }
        float M = fmaxf(fmaxf(m0, m1), fmaxf(m2, m3));

        // exp-sum with per-j max (4 accumulators)
        float s0 = 0.f, s1 = 0.f, s2 = 0.f, s3 = 0.f;
#pragma unroll
        for (int i = 0; i < 32; i += 4) {
            s0 += __expf(ssh[i]     + Tj[i]     - M);
            s1 += __expf(ssh[i + 1] + Tj[i + 1] - M);
            s2 += __expf(ssh[i + 2] + Tj[i + 2] - M);
            s3 += __expf(ssh[i + 3] + Tj[i + 3] - M);
        }
        float S = (s0 + s1) + (s2 + s3);
        float snew = e + M + __logf(S);
        __syncwarp();               // all reads of ssh done before next write
        score = mk ? snew : score;
        e = e_nx; mk = mk_nx;
    }

    // Z = logsumexp(score + trans[STOP])  (global max over j, same as ref)
    float v = score + tr_s[STOPID * 33 + j];
    float Mz = v;
#pragma unroll
    for (int o = 16; o > 0; o >>= 1)
        Mz = fmaxf(Mz, __shfl_xor_sync(0xffffffffu, Mz, o));
    float ez = __expf(v - Mz);
#pragma unroll
    for (int o = 16; o > 0; o >>= 1)
        ez += __shfl_xor_sync(0xffffffffu, ez, o);
    float Z = Mz + __logf(ez);

    // gold path score
    float gacc = 0.f; int lcnt = 0;
    for (int t = j; t < Tn; t += 32) {
        int m = mask[b * Tn + t];
        lcnt += m;
        if (t < Tn - 1 && m) {
            int gn = gold[b * Tn + t + 1];
            int gc = gold[b * Tn + t];
            gacc += g_htag[((size_t)t * Bn + b) * 32 + gn] + tr_s[gn * 33 + gc];
        }
    }
#pragma unroll
    for (int o = 16; o > 0; o >>= 1) {
        gacc += __shfl_xor_sync(0xffffffffu, gacc, o);
        lcnt += __shfl_xor_sync(0xffffffffu, lcnt, o);
    }
    if (j == 0) {
        int last = gold[b * Tn + lcnt - 1];
        out[b] = Z - (gacc + tr_s[STOPID * 33 + last]);
    }
}

// ============================================================
extern "C" void kernel_launch(void* const* d_in, const int* in_sizes, int n_in,
                              void* d_out, int out_size)
{
    const int*   inp   = (const int*)d_in[0];
    const int*   gold  = (const int*)d_in[1];
    const int*   mask  = (const int*)d_in[2];
    const float* emb   = (const float*)d_in[3];
    const float* Wih_f = (const float*)d_in[4];
    const float* Whh_f = (const float*)d_in[5];
    const float* b_f   = (const float*)d_in[6];
    const float* Wih_b = (const float*)d_in[7];
    const float* Whh_b = (const float*)d_in[8];
    const float* b_b   = (const float*)d_in[9];
    const float* W_tag = (const float*)d_in[10];
    const float* b_tag = (const float*)d_in[11];
    const float* trans = (const float*)d_in[12];
    float* out = (float*)d_out;

    cudaFuncSetAttribute(k_lstm, cudaFuncAttributeMaxDynamicSharedMemorySize, LSTM_SMEM);
    cudaFuncSetAttribute(k_tag,  cudaFuncAttributeMaxDynamicSharedMemorySize, TAG_SMEM);

    k_input_gemm<<<dim3(256, 16, 1), 256>>>(inp, emb, Wih_f, b_f, Wih_b, b_b);
    k_lstm<<<dim3(8, 16, 1), 256, LSTM_SMEM>>>(mask, Whh_f, Whh_b);
    k_tag<<<4096, 256, TAG_SMEM>>>(mask, W_tag, b_tag);
    k_crf<<<64, 32>>>(mask, gold, trans, out);
}